// round 3
// baseline (speedup 1.0000x reference)
#include <cuda_runtime.h>

// Model_NPZD_68401649156380 — R3: one batch per block, 8 blocks/SM so the
// gather (DRAM) and recurrence (latency-chain) phases of different blocks
// overlap, keeping HBM busy.
//
// idx(w,s) = 168w + 3s (exact) => compact j = 56w + s, col = 3j, j < 2912.

#define NB      2048
#define NWK     52
#define NHRS    8760
#define DT      0.125f
#define NT      128                 // threads per block
#define NJ      2912                // compacted columns per batch
#define WPAD    57                  // padded per-w stride
#define SFLT2   (NWK * WPAD)        // 2964 float2 = 23712 B
#define SMEM_BYTES (SFLT2 * sizeof(float2))

__global__ __launch_bounds__(NT, 8) void npzd_kernel(
    const float* __restrict__ X_in,     // (B, 52, 5, 1)
    const float* __restrict__ gf,       // (B, 8760)
    const float* __restrict__ gm,       // (B, 8760)
    const float* __restrict__ pv,       // (B, 10)
    float* __restrict__ out)            // (B, 52, 4, 8)
{
    extern __shared__ float2 sbuf[];    // [52][57]
    const int tid = threadIdx.x;
    const int b   = blockIdx.x;

    // ---- Phase 1: gather compacted forcing (stride-12B, ~3 lines/warp-LDG) ----
    {
        const float* fb = gf + (size_t)b * NHRS;
        const float* mb = gm + (size_t)b * NHRS;
        #pragma unroll 4
        for (int j = tid; j < NJ; j += NT) {
            int w = j / 56;
            int s = j - w * 56;
            float fv = fb[3 * j];      // independent loads -> high MLP
            float mv = mb[3 * j];
            sbuf[w * WPAD + s] = make_float2(fv, mv);
        }
    }
    __syncthreads();

    // ---- Phase 2: 56-step Euler recurrence from smem ----
    float o[4][8];
    if (tid < NWK) {
        const int w = tid;

        const float* p = pv + b * 10;
        const float chiC   = p[0];
        const float rho2   = p[1] * 2.0f;
        const float gam01  = p[2] * 0.1f;
        const float lam005 = p[3] * 0.05f;
        const float eps01  = p[4] * 0.1f;
        const float alp03  = p[5] * 0.3f;
        const float bet06  = p[6] * 0.6f;
        const float eta015 = p[7] * 0.15f;
        const float phi04  = p[8] * 0.4f;
        const float zet01  = p[9] * 0.1f;
        const float rem    = 1.0f - alp03 - bet06;

        const float* xi = X_in + ((size_t)(b * NWK + w)) * 5;
        float N = xi[1], P = xi[2], Z = xi[3], D = xi[4];

        const float2* sp = sbuf + w * WPAD;

        o[0][0] = N; o[1][0] = P; o[2][0] = Z; o[3][0] = D;
        int s = 0;
        #pragma unroll 1
        for (int k = 1; k <= 7; ++k) {
            #pragma unroll
            for (int i = 0; i < 8; ++i, ++s) {
                float2 fm = sp[s];
                float ft = fm.x, mt = fm.y;

                float Pc = fmaxf(0.01f, P);
                float Zc = fmaxf(0.01f, Z);
                float gN = N / (chiC + N);
                float zg = rho2 * (1.0f - __expf(-lam005 * Pc)) * Zc;
                float up = gN * ft * Pc;                    // Vm = 1

                float Nn = N + DT * (-up + alp03 * zg + eps01 * P + gam01 * Z
                                     + phi04 * D + mt * (8.0f - N));   // Q0 = 8
                float Pn = P + DT * (up - zg - eps01 * P - eta015 * P - mt * P);
                float Zn = Z + DT * (bet06 * zg - gam01 * Z - mt * Z);
                float Dn = D + DT * (eta015 * P + rem * zg - phi04 * D
                                     - zet01 * D - mt * D);
                N = Nn; P = Pn; Z = Zn; D = Dn;
            }
            o[0][k] = N; o[1][k] = P; o[2][k] = Z; o[3][k] = D;
        }
    }
    __syncthreads();   // sbuf reads done; safe to reuse

    // ---- Phase 3: transpose through smem, coalesced output stores ----
    float* obuf = (float*)sbuf;          // 52*33 floats = 6.9 KB, fits
    if (tid < NWK) {
        float* ob = obuf + tid * 33;     // pad 33: conflict-free
        #pragma unroll
        for (int c = 0; c < 4; ++c)
            #pragma unroll
            for (int k = 0; k < 8; ++k)
                ob[c * 8 + k] = o[c][k];
    }
    __syncthreads();

    // block output region: 52*32 = 1664 contiguous floats
    float* outb = out + (size_t)b * (NWK * 32);
    #pragma unroll
    for (int i = tid; i < NWK * 32; i += NT) {
        int t2 = i >> 5;
        int m  = i & 31;
        outb[i] = obuf[t2 * 33 + m];
    }
}

extern "C" void kernel_launch(void* const* d_in, const int* in_sizes, int n_in,
                              void* d_out, int out_size)
{
    (void)in_sizes; (void)n_in; (void)out_size;
    const float* X_in = (const float*)d_in[0];
    const float* gf   = (const float*)d_in[1];
    const float* gm   = (const float*)d_in[2];
    const float* pvv  = (const float*)d_in[3];
    float* out        = (float*)d_out;

    cudaFuncSetAttribute(npzd_kernel,
                         cudaFuncAttributeMaxDynamicSharedMemorySize,
                         (int)SMEM_BYTES);
    npzd_kernel<<<NB, NT, SMEM_BYTES>>>(X_in, gf, gm, pvv, out);
}